// round 9
// baseline (speedup 1.0000x reference)
#include <cuda_runtime.h>
#include <cuda_bf16.h>
#include <cstdint>
#include <math.h>

// ---------------- problem constants ----------------
#define C_DIM   256
#define M_CLS   256
#define HW      16384
#define N_PIX   262144
#define TILE_P  128
#define KB      32                    // channels per A chunk
#define NKS     (C_DIM / KB)          // 8
#define NBLOCKS (N_PIX / TILE_P)      // 2048
#define NTHREADS 256
#define GRID    152                   // persistent: one CTA per SM
#define INV_T   14.2857142857142857f  // 1/0.07

// ---------------- smem layout (bytes) ----------------
#define SM_B    0
#define B_BYTES (M_CLS * C_DIM * 2)        // 131072
#define A_STRIDE 80                        // 64B data + 16B pad: conflict-free ldmatrix
#define A_BUF   (TILE_P * A_STRIDE)        // 10240
#define SM_A0   (B_BYTES)                  // 131072
#define SM_A1   (SM_A0 + A_BUF)            // 141312
#define SM_RED  (SM_A1 + A_BUF)            // 151552: sn[4][128], sp[4][128], wpart[8]
#define SMEM_BYTES (SM_RED + 4096 + 64)    // 155712

__device__ double g_sum[GRID];
__device__ float  g_cnt[GRID];
__device__ __align__(16) __nv_bfloat16 g_queue_bf[M_CLS * C_DIM];
__device__ unsigned int g_done;   // zero-init; reset by last CTA each launch

__device__ __forceinline__ uint32_t smem_u32(const void* p) {
    uint32_t a;
    asm("{ .reg .u64 t; cvta.to.shared.u64 t, %1; cvt.u32.u64 %0, t; }" : "=r"(a) : "l"(p));
    return a;
}
__device__ __forceinline__ uint32_t pkbf2(float x, float y) {
    __nv_bfloat162 h = __floats2bfloat162_rn(x, y);
    return *(uint32_t*)&h;
}
#define CP_ASYNC16(dst, src) \
    asm volatile("cp.async.cg.shared.global [%0], [%1], 16;" :: "r"(dst), "l"(src) : "memory")
#define CP_COMMIT()  asm volatile("cp.async.commit_group;" ::: "memory")
#define CP_WAIT0()   asm volatile("cp.async.wait_group 0;" ::: "memory")

#define LDMATRIX_X4(r0, r1, r2, r3, addr) \
    asm volatile("ldmatrix.sync.aligned.m8n8.x4.shared.b16 {%0,%1,%2,%3}, [%4];" \
                 : "=r"(r0), "=r"(r1), "=r"(r2), "=r"(r3) : "r"(addr))

#define MMA16816(c, a0, a1, a2, a3, b0, b1) \
    asm volatile("mma.sync.aligned.m16n8k16.row.col.f32.bf16.bf16.f32 " \
                 "{%0,%1,%2,%3}, {%4,%5,%6,%7}, {%8,%9}, {%0,%1,%2,%3};" \
                 : "+f"((c)[0]), "+f"((c)[1]), "+f"((c)[2]), "+f"((c)[3]) \
                 : "r"(a0), "r"(a1), "r"(a2), "r"(a3), "r"(b0), "r"(b1))

// ---- pre-pass: queue f32 -> bf16 ----
__global__ void queue_to_bf16_kernel(const float* __restrict__ queue)
{
    int i = (blockIdx.x * blockDim.x + threadIdx.x) * 2;
    float2 v = *(const float2*)(queue + i);
    __nv_bfloat162 b;
    b.x = __float2bfloat16(v.x);
    b.y = __float2bfloat16(v.y);
    *(__nv_bfloat162*)(g_queue_bf + i) = b;
}

__global__ __launch_bounds__(NTHREADS, 1)
void pcl_persist_kernel(const float* __restrict__ feats,
                        const int*   __restrict__ labels,
                        float*       __restrict__ out)
{
    extern __shared__ char smem[];
    const uint32_t sb   = smem_u32(smem);
    const int tid  = threadIdx.x;
    const int warp = tid >> 5;
    const int lane = tid & 31;

    // ---- B staging ONCE: 128KB queue via cp.async, class-permuted + swizzled ----
    // Within each 64-class group: physical p6 = 16t + 2ni + e stored at logical
    // slot 8ni + 2t + e, so a thread's 16 epilogue classes are physically
    // contiguous [wn*64 + 16t, +16) -> 4 int4 label loads.
    {
        #pragma unroll
        for (int i = 0; i < 32; i++) {
            int q    = tid + NTHREADS * i;       // 0..8191 16B-chunks
            int cls  = q >> 5;                   // physical class
            int c    = q & 31;
            int p6   = cls & 63;
            int slot = (((p6 >> 1) & 7) << 3) | (((p6 >> 4) & 3) << 1) | (p6 & 1);
            int lrow = (cls & ~63) | slot;       // logical smem row
            uint32_t dst = sb + SM_B + lrow * 512 + ((c ^ (lrow & 7)) << 4);
            const void* src = (const char*)g_queue_bf + cls * 512 + c * 16;
            CP_ASYNC16(dst, src);
        }
        CP_COMMIT();
    }

    // ---- A staging roles: thread = (ch4 = 4*(tid&7), p4 = 4*(tid>>3)) ----
    // Per chunk: 4 x LDG.128 (4 consecutive pixels x 4 channels), then
    // register transpose -> 4 x STS.64 into 80B-stride rows.
    const int ch4 = (tid & 7) * 4;     // channel base within chunk (0..28)
    const int p4  = (tid >> 3) * 4;    // pixel base (0..124)

    float4 f4[4];
    auto loadA = [&](const float* fb, int ks) {
        #pragma unroll
        for (int j = 0; j < 4; j++)
            f4[j] = __ldg((const float4*)(fb + (size_t)(ks * KB + ch4 + j) * HW + p4));
    };
    auto storeA = [&](uint32_t abase) {
        const float* fp = (const float*)f4;   // fp[j*4 + p]
        #pragma unroll
        for (int p = 0; p < 4; p++) {
            uint32_t w0 = pkbf2(fp[0 * 4 + p], fp[1 * 4 + p]);
            uint32_t w1 = pkbf2(fp[2 * 4 + p], fp[3 * 4 + p]);
            asm volatile("st.shared.v2.b32 [%0], {%1,%2};"
                         :: "r"(abase + (p4 + p) * A_STRIDE + ch4 * 2),
                            "r"(w0), "r"(w1) : "memory");
        }
    };

    // ---- warp tiling: 8 warps = 2(pix) x 4(cls); warp tile 64 pix x 64 cls ----
    const int wm = warp & 1;     // pixel coord -> rows wm*64..+63
    const int wn = warp >> 1;    // class coord -> cols wn*64..+63

    // A ldmatrix: row = wm*64 + mi*16 + (lane&15), col 16B-unit = kf*2 + (lane>>4)
    const int arow_l = wm * 64 + (lane & 15);
    const int ksel   = lane >> 4;

    // B ldmatrix lane addressing (unchanged from R7; 512B rows, XOR swizzle)
    const int bg   = lane & 7;
    const int bsel = lane >> 3;
    const int bofs = bg + ((bsel >= 2) ? 8 : 0);
    const int bkh  = bsel & 1;

    const int g = lane >> 2;
    const int t = lane & 3;
    float* red_sn = (float*)(smem + SM_RED);            // [4][128]
    float* red_sp = (float*)(smem + SM_RED + 2048);     // [4][128]
    float* wpart  = (float*)(smem + SM_RED + 4096);     // [8]

    double acc_s = 0.0;
    float  acc_c = 0.0f;

    // ---- prologue for first tile ----
    int tile = blockIdx.x;
    const float* fbase = feats + (size_t)((tile * TILE_P) / HW) * C_DIM * HW
                               + ((tile * TILE_P) % HW);
    loadA(fbase, 0);
    storeA(sb + SM_A0);
    CP_WAIT0();
    __syncthreads();

    // ---- persistent tile loop ----
    #pragma unroll 1
    for (; tile < NBLOCKS; tile += GRID) {
        const int pix0 = tile * TILE_P;
        const int next_tile = tile + GRID;
        const float* fbase_next =
            (next_tile < NBLOCKS)
                ? feats + (size_t)((next_tile * TILE_P) / HW) * C_DIM * HW
                        + ((next_tile * TILE_P) % HW)
                : fbase;

        float acc[4][8][4];
        #pragma unroll
        for (int mi = 0; mi < 4; mi++)
            #pragma unroll
            for (int ni = 0; ni < 8; ni++)
                #pragma unroll
                for (int r = 0; r < 4; r++) acc[mi][ni][r] = 0.0f;

        // ---- mainloop: 8 chunks, double-buffered A, cross-tile prefetch ----
        #pragma unroll 1
        for (int ks = 0; ks < NKS; ks++) {
            const bool have_next = (ks < NKS - 1) || (next_tile < NBLOCKS);
            if (ks < NKS - 1)           loadA(fbase, ks + 1);
            else if (have_next)         loadA(fbase_next, 0);

            const uint32_t acur = sb + ((ks & 1) ? SM_A1 : SM_A0);
            #pragma unroll
            for (int kf = 0; kf < 2; kf++) {
                uint32_t afr[4][4];
                #pragma unroll
                for (int mi = 0; mi < 4; mi++) {
                    uint32_t addr = acur + (arow_l + mi * 16) * A_STRIDE +
                                    (kf * 2 + ksel) * 16;
                    LDMATRIX_X4(afr[mi][0], afr[mi][1], afr[mi][2], afr[mi][3], addr);
                }
                const uint32_t kchunk = ks * 4 + kf * 2 + bkh;
                #pragma unroll
                for (int nt = 0; nt < 4; nt++) {
                    const int lcls = wn * 64 + nt * 16 + bofs;
                    uint32_t b0, b1, b2, b3;
                    uint32_t addr = sb + SM_B + lcls * 512 +
                                    ((kchunk ^ (uint32_t)(lcls & 7)) << 4);
                    LDMATRIX_X4(b0, b1, b2, b3, addr);
                    #pragma unroll
                    for (int mi = 0; mi < 4; mi++) {
                        MMA16816(acc[mi][nt * 2 + 0], afr[mi][0], afr[mi][1], afr[mi][2], afr[mi][3], b0, b1);
                        MMA16816(acc[mi][nt * 2 + 1], afr[mi][0], afr[mi][1], afr[mi][2], afr[mi][3], b2, b3);
                    }
                }
            }

            if (have_next) {
                storeA(sb + (((ks + 1) & 1) ? SM_A1 : SM_A0));
                __syncthreads();
            }
        }

        // ---- register epilogue: permuted labels -> 4 int4 loads per (mi,h) ----
        // acc[mi][ni][h*2+e] <-> physical class wn*64 + 16t + 2ni + e
        #pragma unroll
        for (int mi = 0; mi < 4; mi++) {
            #pragma unroll
            for (int h = 0; h < 2; h++) {
                const int pixel = wm * 64 + mi * 16 + h * 8 + g;
                const int4* lp = (const int4*)(labels +
                    (size_t)(pix0 + pixel) * M_CLS + wn * 64 + t * 16);
                int4 l0 = __ldg(lp);
                int4 l1 = __ldg(lp + 1);
                int4 l2 = __ldg(lp + 2);
                int4 l3 = __ldg(lp + 3);
                int l[16] = { l0.x, l0.y, l0.z, l0.w, l1.x, l1.y, l1.z, l1.w,
                              l2.x, l2.y, l2.z, l2.w, l3.x, l3.y, l3.z, l3.w };
                float sn = 0.0f, sp = 0.0f;
                #pragma unroll
                for (int ni = 0; ni < 8; ni++) {
                    #pragma unroll
                    for (int e = 0; e < 2; e++) {
                        int   lv = l[2 * ni + e];
                        float v  = acc[mi][ni][h * 2 + e] * INV_T;
                        float ev = __expf(lv ? -v : v);
                        if (lv) sp += ev; else sn += ev;
                    }
                }
                sn += __shfl_xor_sync(0xFFFFFFFFu, sn, 1);
                sn += __shfl_xor_sync(0xFFFFFFFFu, sn, 2);
                sp += __shfl_xor_sync(0xFFFFFFFFu, sp, 1);
                sp += __shfl_xor_sync(0xFFFFFFFFu, sp, 2);
                if (t == 0) {
                    red_sn[wn * 128 + pixel] = sn;
                    red_sp[wn * 128 + pixel] = sp;
                }
            }
        }
        __syncthreads();

        float th_loss = 0.0f, th_cnt = 0.0f;
        if (tid < 128) {
            float tsn = red_sn[tid] + red_sn[128 + tid] + red_sn[256 + tid] + red_sn[384 + tid];
            float tsp = red_sp[tid] + red_sp[128 + tid] + red_sp[256 + tid] + red_sp[384 + tid];
            float loss = logf(tsn * tsp + 1.0f);
            th_loss = loss;
            th_cnt  = (loss != 0.0f) ? 1.0f : 0.0f;
            #pragma unroll
            for (int o = 16; o > 0; o >>= 1) {
                th_loss += __shfl_xor_sync(0xFFFFFFFFu, th_loss, o);
                th_cnt  += __shfl_xor_sync(0xFFFFFFFFu, th_cnt,  o);
            }
            if (lane == 0) { wpart[warp] = th_loss; wpart[warp + 4] = th_cnt; }
        }
        __syncthreads();
        if (tid == 0) {
            acc_s += (double)(wpart[0] + wpart[1] + wpart[2] + wpart[3]);
            acc_c += wpart[4] + wpart[5] + wpart[6] + wpart[7];
        }

        fbase = fbase_next;
    }

    // ---- publish per-CTA totals; last CTA reduces ----
    __shared__ bool is_last;
    if (tid == 0) {
        g_sum[blockIdx.x] = acc_s;
        g_cnt[blockIdx.x] = acc_c;
        __threadfence();
        unsigned old = atomicAdd(&g_done, 1u);
        is_last = (old == GRID - 1);
    }
    __syncthreads();

    if (is_last) {
        __shared__ double dsum[GRID];
        __shared__ float  fcnt[GRID];
        if (tid < GRID) {
            dsum[tid] = g_sum[tid];
            fcnt[tid] = g_cnt[tid];
        }
        __syncthreads();
        if (tid == 0) {
            double s = 0.0;
            float  c = 0.0f;
            #pragma unroll 1
            for (int i = 0; i < GRID; i++) { s += dsum[i]; c += fcnt[i]; }
            out[0] = (c == 0.0f) ? 0.0f : (float)(s / (double)fmaxf(c, 1.0f));
            __threadfence();
            g_done = 0;   // reset for graph replay
        }
    }
}

extern "C" void kernel_launch(void* const* d_in, const int* in_sizes, int n_in,
                              void* d_out, int out_size)
{
    // metadata.txt order: feats (f32), queue (f32), labels (i32).
    // feats and labels have identical element counts — positional ID only.
    const float* feats  = (const float*)d_in[0];
    const float* queue  = (const float*)d_in[1];
    const int*   labels = (const int*)d_in[2];

    cudaFuncSetAttribute(pcl_persist_kernel,
                         cudaFuncAttributeMaxDynamicSharedMemorySize, SMEM_BYTES);

    queue_to_bf16_kernel<<<M_CLS * C_DIM / (2 * 256), 256>>>(queue);
    pcl_persist_kernel<<<GRID, NTHREADS, SMEM_BYTES>>>(feats, labels, (float*)d_out);
}

// round 10
// speedup vs baseline: 1.6301x; 1.6301x over previous
#include <cuda_runtime.h>
#include <cuda_bf16.h>
#include <cstdint>
#include <math.h>

// ---------------- problem constants ----------------
#define C_DIM   256
#define M_CLS   256
#define HW      16384
#define N_PIX   262144
#define TILE_P  128
#define KB      32                    // channels per A chunk
#define NKS     (C_DIM / KB)          // 8
#define NTILES  (N_PIX / TILE_P)      // 2048
#define NTASKS  (NTILES * 2)          // 4096 (tile x class-half)
#define NTHREADS 256
#define GRID    304                   // persistent: two CTAs per SM
#define INV_T   14.2857142857142857f  // 1/0.07

// ---------------- per-CTA smem layout (bytes) ----------------
#define SM_B    0
#define B_BYTES (128 * C_DIM * 2)          // 65536 (this CTA's 128-class half)
#define SM_A0   (B_BYTES)                  // 65536  A: 128px x 32ch bf16 = 8192
#define SM_A1   (SM_A0 + TILE_P * KB * 2)  // 73728
#define SM_RED  (SM_A1 + TILE_P * KB * 2)  // 81920: sn[2][128], sp[2][128]
#define SMEM_BYTES (SM_RED + 2048 + 64)    // 84032

__device__ __align__(16) __nv_bfloat16 g_queue_bf[M_CLS * C_DIM];
__device__ __align__(16) float2 g_part[N_PIX * 2];   // (sn,sp) per (pixel, half): 4MB
__device__ double g_bsum[256];
__device__ float  g_bcnt[256];
__device__ unsigned int g_done;   // zero-init; reset by last block of final kernel

__device__ __forceinline__ uint32_t smem_u32(const void* p) {
    uint32_t a;
    asm("{ .reg .u64 t; cvta.to.shared.u64 t, %1; cvt.u32.u64 %0, t; }" : "=r"(a) : "l"(p));
    return a;
}
__device__ __forceinline__ uint32_t pkbf2(float x, float y) {
    __nv_bfloat162 h = __floats2bfloat162_rn(x, y);
    return *(uint32_t*)&h;
}
#define CP_ASYNC16(dst, src) \
    asm volatile("cp.async.cg.shared.global [%0], [%1], 16;" :: "r"(dst), "l"(src) : "memory")
#define CP_COMMIT()  asm volatile("cp.async.commit_group;" ::: "memory")
#define CP_WAIT0()   asm volatile("cp.async.wait_group 0;" ::: "memory")

#define LDMATRIX_X4(r0, r1, r2, r3, addr) \
    asm volatile("ldmatrix.sync.aligned.m8n8.x4.shared.b16 {%0,%1,%2,%3}, [%4];" \
                 : "=r"(r0), "=r"(r1), "=r"(r2), "=r"(r3) : "r"(addr))

#define MMA16816(c, a0, a1, a2, a3, b0, b1) \
    asm volatile("mma.sync.aligned.m16n8k16.row.col.f32.bf16.bf16.f32 " \
                 "{%0,%1,%2,%3}, {%4,%5,%6,%7}, {%8,%9}, {%0,%1,%2,%3};" \
                 : "+f"((c)[0]), "+f"((c)[1]), "+f"((c)[2]), "+f"((c)[3]) \
                 : "r"(a0), "r"(a1), "r"(a2), "r"(a3), "r"(b0), "r"(b1))

// ---- pre-pass: queue f32 -> bf16 ----
__global__ void queue_to_bf16_kernel(const float* __restrict__ queue)
{
    int i = (blockIdx.x * blockDim.x + threadIdx.x) * 2;
    float2 v = *(const float2*)(queue + i);
    __nv_bfloat162 b;
    b.x = __float2bfloat16(v.x);
    b.y = __float2bfloat16(v.y);
    *(__nv_bfloat162*)(g_queue_bf + i) = b;
}

// ---- main: persistent, 2 CTAs per tile (class halves), warp tile 32x64 ----
__global__ __launch_bounds__(NTHREADS, 2)
void pcl_main_kernel(const float* __restrict__ feats,
                     const int*   __restrict__ labels)
{
    extern __shared__ char smem[];
    const uint32_t sb   = smem_u32(smem);
    const int tid  = threadIdx.x;
    const int warp = tid >> 5;
    const int lane = tid & 31;

    const int task0 = blockIdx.x;
    const int half  = task0 & 1;            // class half is FIXED per CTA (stride 304 even)

    // ---- B staging ONCE: this half's 64KB, class-permuted + swizzled ----
    // Within each 64-class group: physical p6 = 16t + 2ni + e stored at logical
    // slot 8ni + 2t + e  ->  a thread's 16 epilogue classes are contiguous.
    {
        #pragma unroll
        for (int i = 0; i < 16; i++) {
            int q    = tid + NTHREADS * i;       // 0..4095 16B-chunks
            int cls  = q >> 5;                   // local class 0..127
            int c    = q & 31;
            int p6   = cls & 63;
            int slot = (((p6 >> 1) & 7) << 3) | (((p6 >> 4) & 3) << 1) | (p6 & 1);
            int lrow = (cls & ~63) | slot;       // logical smem row
            uint32_t dst = sb + SM_B + lrow * 512 + ((c ^ (lrow & 7)) << 4);
            const void* src = (const char*)g_queue_bf + (half * 128 + cls) * 512 + c * 16;
            CP_ASYNC16(dst, src);
        }
        CP_COMMIT();
    }

    // ---- A staging roles: thread = (chg 0..3, pix pair m 0..63) ----
    // 8 x LDG.64 (2 pixels x 8 channels), then 2 x STS.128 (one per pixel).
    const int m2  = (tid & 63) * 2;    // pixel pair base
    const int chg = tid >> 6;          // 16B chunk / 8-channel group (0..3)

    float2 areg[8];
    auto loadA = [&](const float* fb, int ks) {
        #pragma unroll
        for (int j = 0; j < 8; j++)
            areg[j] = __ldg((const float2*)(fb + (size_t)(ks * KB + chg * 8 + j) * HW + m2));
    };
    auto storeA = [&](uint32_t abase) {
        #pragma unroll
        for (int p = 0; p < 2; p++) {
            const float* fp = (const float*)areg;   // fp[j*2 + p]
            uint4 w;
            w.x = pkbf2(fp[0 * 2 + p], fp[1 * 2 + p]);
            w.y = pkbf2(fp[2 * 2 + p], fp[3 * 2 + p]);
            w.z = pkbf2(fp[4 * 2 + p], fp[5 * 2 + p]);
            w.w = pkbf2(fp[6 * 2 + p], fp[7 * 2 + p]);
            int pix = m2 + p;
            uint32_t off = pix * 64 + ((chg ^ ((pix >> 1) & 3)) << 4);
            asm volatile("st.shared.v4.b32 [%0], {%1,%2,%3,%4};"
                         :: "r"(abase + off), "r"(w.x), "r"(w.y), "r"(w.z), "r"(w.w) : "memory");
        }
    };

    // ---- warp tiling: 8 warps = 4(pix) x 2(cls); warp tile 32 pix x 64 cls ----
    const int wm = warp & 3;
    const int wn = warp >> 2;           // 0..1 (within this CTA's 128-class half)

    const int arow0 = wm * 32 + (lane & 15);
    const int ksel  = lane >> 4;
    const uint32_t a_ld_base[2] = { (uint32_t)(arow0 * 64),
                                    (uint32_t)((arow0 + 16) * 64) };
    const uint32_t a_swz[2] = { (uint32_t)((arow0 >> 1) & 3),
                                (uint32_t)(((arow0 + 16) >> 1) & 3) };

    const int bg   = lane & 7;
    const int bsel = lane >> 3;
    const int bofs = bg + ((bsel >= 2) ? 8 : 0);
    const int bkh  = bsel & 1;

    const int g = lane >> 2;
    const int t = lane & 3;
    float* red_sn = (float*)(smem + SM_RED);            // [2][128]
    float* red_sp = (float*)(smem + SM_RED + 1024);     // [2][128]

    // ---- prologue for first task ----
    int task = task0;
    int tile = task >> 1;
    const float* fbase = feats + (size_t)((tile * TILE_P) / HW) * C_DIM * HW
                               + ((tile * TILE_P) % HW);
    loadA(fbase, 0);
    storeA(sb + SM_A0);
    CP_WAIT0();
    __syncthreads();

    // ---- persistent task loop (stride GRID keeps half fixed; tile += 152) ----
    #pragma unroll 1
    for (; task < NTASKS; task += GRID) {
        tile = task >> 1;
        const int pix0 = tile * TILE_P;
        const int next_task = task + GRID;
        const float* fbase_next =
            (next_task < NTASKS)
                ? feats + (size_t)(((next_task >> 1) * TILE_P) / HW) * C_DIM * HW
                        + (((next_task >> 1) * TILE_P) % HW)
                : fbase;

        float acc[2][8][4];
        #pragma unroll
        for (int mi = 0; mi < 2; mi++)
            #pragma unroll
            for (int ni = 0; ni < 8; ni++)
                #pragma unroll
                for (int r = 0; r < 4; r++) acc[mi][ni][r] = 0.0f;

        // ---- mainloop: 8 chunks, double-buffered A, cross-task prefetch ----
        #pragma unroll 1
        for (int ks = 0; ks < NKS; ks++) {
            const bool have_next = (ks < NKS - 1) || (next_task < NTASKS);
            if (ks < NKS - 1)           loadA(fbase, ks + 1);
            else if (have_next)         loadA(fbase_next, 0);

            const uint32_t acur = sb + ((ks & 1) ? SM_A1 : SM_A0);
            #pragma unroll
            for (int kf = 0; kf < 2; kf++) {
                uint32_t afr[2][4];
                #pragma unroll
                for (int mi = 0; mi < 2; mi++) {
                    uint32_t addr = acur + a_ld_base[mi] +
                                    (((uint32_t)(kf * 2 + ksel) ^ a_swz[mi]) << 4);
                    LDMATRIX_X4(afr[mi][0], afr[mi][1], afr[mi][2], afr[mi][3], addr);
                }
                const uint32_t kchunk = ks * 4 + kf * 2 + bkh;
                #pragma unroll
                for (int nt = 0; nt < 4; nt++) {
                    const int lcls = wn * 64 + nt * 16 + bofs;   // local class row
                    uint32_t b0, b1, b2, b3;
                    uint32_t addr = sb + SM_B + lcls * 512 +
                                    ((kchunk ^ (uint32_t)(lcls & 7)) << 4);
                    LDMATRIX_X4(b0, b1, b2, b3, addr);
                    #pragma unroll
                    for (int mi = 0; mi < 2; mi++) {
                        MMA16816(acc[mi][nt * 2 + 0], afr[mi][0], afr[mi][1], afr[mi][2], afr[mi][3], b0, b1);
                        MMA16816(acc[mi][nt * 2 + 1], afr[mi][0], afr[mi][1], afr[mi][2], afr[mi][3], b2, b3);
                    }
                }
            }

            if (have_next) {
                storeA(sb + (((ks + 1) & 1) ? SM_A1 : SM_A0));
                __syncthreads();
            }
        }

        // ---- register epilogue: acc[mi][ni][h*2+e] <-> physical class
        //      half*128 + wn*64 + 16t + 2ni + e ----
        #pragma unroll
        for (int mi = 0; mi < 2; mi++) {
            #pragma unroll
            for (int h = 0; h < 2; h++) {
                const int pixel = wm * 32 + mi * 16 + h * 8 + g;
                const int4* lp = (const int4*)(labels +
                    (size_t)(pix0 + pixel) * M_CLS + half * 128 + wn * 64 + t * 16);
                int4 l0 = __ldg(lp);
                int4 l1 = __ldg(lp + 1);
                int4 l2 = __ldg(lp + 2);
                int4 l3 = __ldg(lp + 3);
                int l[16] = { l0.x, l0.y, l0.z, l0.w, l1.x, l1.y, l1.z, l1.w,
                              l2.x, l2.y, l2.z, l2.w, l3.x, l3.y, l3.z, l3.w };
                float sn = 0.0f, sp = 0.0f;
                #pragma unroll
                for (int ni = 0; ni < 8; ni++) {
                    #pragma unroll
                    for (int e = 0; e < 2; e++) {
                        int   lv = l[2 * ni + e];
                        float v  = acc[mi][ni][h * 2 + e] * INV_T;
                        float ev = __expf(lv ? -v : v);
                        if (lv) sp += ev; else sn += ev;
                    }
                }
                sn += __shfl_xor_sync(0xFFFFFFFFu, sn, 1);
                sn += __shfl_xor_sync(0xFFFFFFFFu, sn, 2);
                sp += __shfl_xor_sync(0xFFFFFFFFu, sp, 1);
                sp += __shfl_xor_sync(0xFFFFFFFFu, sp, 2);
                if (t == 0) {
                    red_sn[wn * 128 + pixel] = sn;
                    red_sp[wn * 128 + pixel] = sp;
                }
            }
        }
        __syncthreads();

        // combine the 2 class-slices; publish partial (sn, sp) for this half
        if (tid < 128) {
            float tsn = red_sn[tid] + red_sn[128 + tid];
            float tsp = red_sp[tid] + red_sp[128 + tid];
            g_part[(size_t)(pix0 + tid) * 2 + half] = make_float2(tsn, tsp);
        }
        __syncthreads();

        fbase = fbase_next;
    }
}

// ---- final: combine halves, loss, deterministic mean ----
__global__ __launch_bounds__(1024)
void pcl_final_kernel(float* __restrict__ out)
{
    const int tid = threadIdx.x;
    const int p   = blockIdx.x * 1024 + tid;

    float2 a = g_part[(size_t)p * 2 + 0];
    float2 b = g_part[(size_t)p * 2 + 1];
    float sn = a.x + b.x;
    float sp = a.y + b.y;
    float loss = logf(sn * sp + 1.0f);
    float th_loss = loss;
    float th_cnt  = (loss != 0.0f) ? 1.0f : 0.0f;

    __shared__ float ssum[1024];
    __shared__ float scnt[1024];
    ssum[tid] = th_loss;
    scnt[tid] = th_cnt;
    __syncthreads();
    for (int o = 512; o > 0; o >>= 1) {
        if (tid < o) { ssum[tid] += ssum[tid + o]; scnt[tid] += scnt[tid + o]; }
        __syncthreads();
    }

    __shared__ bool is_last;
    if (tid == 0) {
        g_bsum[blockIdx.x] = (double)ssum[0];
        g_bcnt[blockIdx.x] = scnt[0];
        __threadfence();
        unsigned old = atomicAdd(&g_done, 1u);
        is_last = (old == 255);
    }
    __syncthreads();

    if (is_last && tid == 0) {
        double s = 0.0;
        float  c = 0.0f;
        #pragma unroll 1
        for (int i = 0; i < 256; i++) { s += g_bsum[i]; c += g_bcnt[i]; }
        out[0] = (c == 0.0f) ? 0.0f : (float)(s / (double)fmaxf(c, 1.0f));
        __threadfence();
        g_done = 0;   // reset for graph replay
    }
}

extern "C" void kernel_launch(void* const* d_in, const int* in_sizes, int n_in,
                              void* d_out, int out_size)
{
    // metadata.txt order: feats (f32), queue (f32), labels (i32).
    // feats and labels have identical element counts — positional ID only.
    const float* feats  = (const float*)d_in[0];
    const float* queue  = (const float*)d_in[1];
    const int*   labels = (const int*)d_in[2];

    cudaFuncSetAttribute(pcl_main_kernel,
                         cudaFuncAttributeMaxDynamicSharedMemorySize, SMEM_BYTES);

    queue_to_bf16_kernel<<<M_CLS * C_DIM / (2 * 256), 256>>>(queue);
    pcl_main_kernel<<<GRID, NTHREADS, SMEM_BYTES>>>(feats, labels);
    pcl_final_kernel<<<N_PIX / 1024, 1024>>>((float*)d_out);
}

// round 11
// speedup vs baseline: 1.8508x; 1.1354x over previous
#include <cuda_runtime.h>
#include <cuda_bf16.h>
#include <cstdint>
#include <math.h>

// ---------------- problem constants ----------------
#define C_DIM   256
#define M_CLS   256
#define HW      16384
#define N_PIX   262144
#define TILE_P  64                     // pixels per GROUP-tile
#define KB      32                     // channels per A chunk
#define NKS     (C_DIM / KB)           // 8
#define NTASKS  (N_PIX / TILE_P)       // 4096
#define NTHREADS 512                   // 2 groups x 256
#define GRID     152                   // persistent: one CTA per SM
#define NGROUPS  (GRID * 2)            // 304 independent task streams
#define SCALE_EX2 20.60992915555662f   // (1/0.07) * log2(e)

// ---------------- smem layout (bytes) ----------------
#define SM_B       0
#define B_BYTES    (M_CLS * C_DIM * 2)     // 131072 (shared by both groups)
#define A_BUF      (TILE_P * 64)           // 4096 per buffer
#define SM_A_BASE  (B_BYTES)               // + g*8192 + buf*4096
#define SM_RED_B   (SM_A_BASE + 4 * A_BUF) // 147456; per group 2560B: sn[256],sp[256],wpart
#define SM_FIN     (SM_RED_B + 2 * 2560)   // 152576: final reduce 256 dbl + 256 flt
#define SMEM_BYTES (SM_FIN + 3072 + 64)    // 155712

__device__ double g_sum[NGROUPS];
__device__ float  g_cnt[NGROUPS];
__device__ __align__(16) __nv_bfloat16 g_queue_bf[M_CLS * C_DIM];
__device__ unsigned int g_done;   // zero-init; reset by winning group each launch

__device__ __forceinline__ uint32_t smem_u32(const void* p) {
    uint32_t a;
    asm("{ .reg .u64 t; cvta.to.shared.u64 t, %1; cvt.u32.u64 %0, t; }" : "=r"(a) : "l"(p));
    return a;
}
__device__ __forceinline__ uint32_t pkbf2(float x, float y) {
    __nv_bfloat162 h = __floats2bfloat162_rn(x, y);
    return *(uint32_t*)&h;
}
__device__ __forceinline__ float ex2(float x) {
    float r;
    asm("ex2.approx.f32 %0, %1;" : "=f"(r) : "f"(x));
    return r;
}
#define BARG(id) asm volatile("bar.sync %0, 256;" :: "r"(id) : "memory")
#define CP_ASYNC16(dst, src) \
    asm volatile("cp.async.cg.shared.global [%0], [%1], 16;" :: "r"(dst), "l"(src) : "memory")
#define CP_COMMIT()  asm volatile("cp.async.commit_group;" ::: "memory")
#define CP_WAIT0()   asm volatile("cp.async.wait_group 0;" ::: "memory")

#define LDMATRIX_X4(r0, r1, r2, r3, addr) \
    asm volatile("ldmatrix.sync.aligned.m8n8.x4.shared.b16 {%0,%1,%2,%3}, [%4];" \
                 : "=r"(r0), "=r"(r1), "=r"(r2), "=r"(r3) : "r"(addr))

#define MMA16816(c, a0, a1, a2, a3, b0, b1) \
    asm volatile("mma.sync.aligned.m16n8k16.row.col.f32.bf16.bf16.f32 " \
                 "{%0,%1,%2,%3}, {%4,%5,%6,%7}, {%8,%9}, {%0,%1,%2,%3};" \
                 : "+f"((c)[0]), "+f"((c)[1]), "+f"((c)[2]), "+f"((c)[3]) \
                 : "r"(a0), "r"(a1), "r"(a2), "r"(a3), "r"(b0), "r"(b1))

// ---- pre-pass: queue f32 -> bf16 ----
__global__ void queue_to_bf16_kernel(const float* __restrict__ queue)
{
    int i = (blockIdx.x * blockDim.x + threadIdx.x) * 2;
    float2 v = *(const float2*)(queue + i);
    __nv_bfloat162 b;
    b.x = __float2bfloat16(v.x);
    b.y = __float2bfloat16(v.y);
    *(__nv_bfloat162*)(g_queue_bf + i) = b;
}

// ---- main: persistent; 2 independent 256-thread groups share one B tile ----
__global__ __launch_bounds__(NTHREADS, 1)
void pcl_main_kernel(const float* __restrict__ feats,
                     const int*   __restrict__ labels,
                     float*       __restrict__ out)
{
    extern __shared__ char smem[];
    __shared__ bool s_last[2];
    const uint32_t sb  = smem_u32(smem);
    const int tid  = threadIdx.x;
    const int g    = tid >> 8;          // group 0/1
    const int tig  = tid & 255;         // thread-in-group
    const int warp = tig >> 5;          // 0..7 within group
    const int lane = tid & 31;
    const int barid = 1 + g;

    // ---- B staging ONCE (whole CTA): 128KB, class-permuted + swizzled ----
    // Within each 64-class group: physical p6 = 16t + 2ni + e stored at logical
    // slot 8ni + 2t + e  ->  a thread's 16 epilogue classes are contiguous.
    {
        #pragma unroll
        for (int i = 0; i < 16; i++) {
            int q    = tid + NTHREADS * i;       // 0..8191 16B-chunks
            int cls  = q >> 5;                   // physical class
            int c    = q & 31;
            int p6   = cls & 63;
            int slot = (((p6 >> 1) & 7) << 3) | (((p6 >> 4) & 3) << 1) | (p6 & 1);
            int lrow = (cls & ~63) | slot;       // logical smem row
            uint32_t dst = sb + SM_B + lrow * 512 + ((c ^ (lrow & 7)) << 4);
            const void* src = (const char*)g_queue_bf + cls * 512 + c * 16;
            CP_ASYNC16(dst, src);
        }
        CP_COMMIT();
    }

    // ---- A staging roles (within group): pix = tig&63, cq = tig>>6 (8 ch) ----
    const int pixA = tig & 63;
    const int cq   = tig >> 6;
    const uint32_t a_st_off = pixA * 64 + ((cq ^ ((pixA >> 1) & 3)) << 4);
    const uint32_t smA[2] = { sb + SM_A_BASE + (uint32_t)g * 2 * A_BUF,
                              sb + SM_A_BASE + (uint32_t)g * 2 * A_BUF + A_BUF };

    float areg[8];
    auto loadA = [&](const float* fb, int ks) {
        #pragma unroll
        for (int j = 0; j < 8; j++)
            areg[j] = __ldg(fb + (size_t)(ks * KB + cq * 8 + j) * HW + pixA);
    };
    auto storeA = [&](uint32_t abase) {
        uint4 w;
        w.x = pkbf2(areg[0], areg[1]);
        w.y = pkbf2(areg[2], areg[3]);
        w.z = pkbf2(areg[4], areg[5]);
        w.w = pkbf2(areg[6], areg[7]);
        asm volatile("st.shared.v4.b32 [%0], {%1,%2,%3,%4};"
                     :: "r"(abase + a_st_off), "r"(w.x), "r"(w.y), "r"(w.z), "r"(w.w) : "memory");
    };

    // ---- warp tiling per group: 8 warps = 2(pix) x 4(cls); tile 32x64 ----
    const int wm = warp & 1;
    const int wn = warp >> 1;

    const int arow0 = wm * 32 + (lane & 15);
    const int ksel  = lane >> 4;
    const uint32_t a_ld_base[2] = { (uint32_t)(arow0 * 64),
                                    (uint32_t)((arow0 + 16) * 64) };
    const uint32_t a_swz[2] = { (uint32_t)((arow0 >> 1) & 3),
                                (uint32_t)(((arow0 + 16) >> 1) & 3) };

    const int bg   = lane & 7;
    const int bsel = lane >> 3;
    const int bofs = bg + ((bsel >= 2) ? 8 : 0);
    const int bkh  = bsel & 1;

    const int gq = lane >> 2;
    const int t  = lane & 3;
    float* red_sn = (float*)(smem + SM_RED_B + g * 2560);          // [4][64]
    float* red_sp = (float*)(smem + SM_RED_B + g * 2560 + 1024);   // [4][64]
    float* wpart  = (float*)(smem + SM_RED_B + g * 2560 + 2048);   // [4]

    double acc_s = 0.0;
    float  acc_c = 0.0f;

    // ---- prologue for first task ----
    const int gid = blockIdx.x * 2 + g;
    int task = gid;
    const float* fbase = feats + (size_t)((task * TILE_P) / HW) * C_DIM * HW
                               + ((task * TILE_P) % HW);
    loadA(fbase, 0);
    storeA(smA[0]);
    CP_WAIT0();
    __syncthreads();   // B visible + both groups' first A staged; last CTA-wide sync

    // ---- persistent task loop (group-independent from here on) ----
    #pragma unroll 1
    for (; task < NTASKS; task += NGROUPS) {
        const int pix0 = task * TILE_P;
        const int next_task = task + NGROUPS;
        const float* fbase_next =
            (next_task < NTASKS)
                ? feats + (size_t)((next_task * TILE_P) / HW) * C_DIM * HW
                        + ((next_task * TILE_P) % HW)
                : fbase;

        float acc[2][8][4];
        #pragma unroll
        for (int mi = 0; mi < 2; mi++)
            #pragma unroll
            for (int ni = 0; ni < 8; ni++)
                #pragma unroll
                for (int r = 0; r < 4; r++) acc[mi][ni][r] = 0.0f;

        // ---- mainloop: 8 chunks, double-buffered A, cross-task prefetch ----
        #pragma unroll 1
        for (int ks = 0; ks < NKS; ks++) {
            const bool have_next = (ks < NKS - 1) || (next_task < NTASKS);
            if (ks < NKS - 1)           loadA(fbase, ks + 1);
            else if (have_next)         loadA(fbase_next, 0);

            const uint32_t acur = smA[ks & 1];
            #pragma unroll
            for (int kf = 0; kf < 2; kf++) {
                uint32_t afr[2][4];
                #pragma unroll
                for (int mi = 0; mi < 2; mi++) {
                    uint32_t addr = acur + a_ld_base[mi] +
                                    (((uint32_t)(kf * 2 + ksel) ^ a_swz[mi]) << 4);
                    LDMATRIX_X4(afr[mi][0], afr[mi][1], afr[mi][2], afr[mi][3], addr);
                }
                const uint32_t kchunk = ks * 4 + kf * 2 + bkh;
                #pragma unroll
                for (int nt = 0; nt < 4; nt++) {
                    const int lcls = wn * 64 + nt * 16 + bofs;
                    uint32_t b0, b1, b2, b3;
                    uint32_t addr = sb + SM_B + lcls * 512 +
                                    ((kchunk ^ (uint32_t)(lcls & 7)) << 4);
                    LDMATRIX_X4(b0, b1, b2, b3, addr);
                    #pragma unroll
                    for (int mi = 0; mi < 2; mi++) {
                        MMA16816(acc[mi][nt * 2 + 0], afr[mi][0], afr[mi][1], afr[mi][2], afr[mi][3], b0, b1);
                        MMA16816(acc[mi][nt * 2 + 1], afr[mi][0], afr[mi][1], afr[mi][2], afr[mi][3], b2, b3);
                    }
                }
            }

            if (have_next) {
                storeA(smA[(ks + 1) & 1]);
                BARG(barid);
            }
        }

        // ---- register epilogue: acc[mi][ni][h*2+e] <-> class wn*64+16t+2ni+e ----
        #pragma unroll
        for (int mi = 0; mi < 2; mi++) {
            #pragma unroll
            for (int h = 0; h < 2; h++) {
                const int pixel = wm * 32 + mi * 16 + h * 8 + gq;
                const int4* lp = (const int4*)(labels +
                    (size_t)(pix0 + pixel) * M_CLS + wn * 64 + t * 16);
                int4 l0 = __ldg(lp);
                int4 l1 = __ldg(lp + 1);
                int4 l2 = __ldg(lp + 2);
                int4 l3 = __ldg(lp + 3);
                int l[16] = { l0.x, l0.y, l0.z, l0.w, l1.x, l1.y, l1.z, l1.w,
                              l2.x, l2.y, l2.z, l2.w, l3.x, l3.y, l3.z, l3.w };
                float sn = 0.0f, sp = 0.0f;
                #pragma unroll
                for (int ni = 0; ni < 8; ni++) {
                    #pragma unroll
                    for (int e = 0; e < 2; e++) {
                        int   lv = l[2 * ni + e];
                        float v  = acc[mi][ni][h * 2 + e] * SCALE_EX2;
                        float ev = ex2(lv ? -v : v);
                        if (lv) sp += ev; else sn += ev;
                    }
                }
                sn += __shfl_xor_sync(0xFFFFFFFFu, sn, 1);
                sn += __shfl_xor_sync(0xFFFFFFFFu, sn, 2);
                sp += __shfl_xor_sync(0xFFFFFFFFu, sp, 1);
                sp += __shfl_xor_sync(0xFFFFFFFFu, sp, 2);
                if (t == 0) {
                    red_sn[wn * 64 + pixel] = sn;
                    red_sp[wn * 64 + pixel] = sp;
                }
            }
        }
        BARG(barid);

        float th_loss = 0.0f, th_cnt = 0.0f;
        if (tig < 64) {    // warps 0 and 1 of the group (fully convergent)
            float tsn = red_sn[tig] + red_sn[64 + tig] + red_sn[128 + tig] + red_sn[192 + tig];
            float tsp = red_sp[tig] + red_sp[64 + tig] + red_sp[128 + tig] + red_sp[192 + tig];
            float loss = logf(tsn * tsp + 1.0f);
            th_loss = loss;
            th_cnt  = (loss != 0.0f) ? 1.0f : 0.0f;
            #pragma unroll
            for (int o = 16; o > 0; o >>= 1) {
                th_loss += __shfl_xor_sync(0xFFFFFFFFu, th_loss, o);
                th_cnt  += __shfl_xor_sync(0xFFFFFFFFu, th_cnt,  o);
            }
            if (lane == 0) { wpart[(tig >> 5) * 2] = th_loss; wpart[(tig >> 5) * 2 + 1] = th_cnt; }
        }
        BARG(barid);
        if (tig == 0) {
            acc_s += (double)(wpart[0] + wpart[2]);
            acc_c += wpart[1] + wpart[3];
        }

        fbase = fbase_next;
    }

    // ---- publish per-group totals; last finishing group reduces ----
    if (tig == 0) {
        g_sum[gid] = acc_s;
        g_cnt[gid] = acc_c;
        __threadfence();
        unsigned old = atomicAdd(&g_done, 1u);
        s_last[g] = (old == NGROUPS - 1);
    }
    BARG(barid);

    if (s_last[g]) {
        double* dsum = (double*)(smem + SM_FIN);          // 256 doubles
        float*  fcnt = (float*)(smem + SM_FIN + 2048);    // 256 floats
        double s = 0.0;
        float  c = 0.0f;
        #pragma unroll 1
        for (int i = tig; i < NGROUPS; i += 256) { s += g_sum[i]; c += g_cnt[i]; }
        dsum[tig] = s;
        fcnt[tig] = c;
        BARG(barid);
        for (int o = 128; o > 0; o >>= 1) {
            if (tig < o) { dsum[tig] += dsum[tig + o]; fcnt[tig] += fcnt[tig + o]; }
            BARG(barid);
        }
        if (tig == 0) {
            float cnt = fcnt[0];
            out[0] = (cnt == 0.0f) ? 0.0f : (float)(dsum[0] / (double)fmaxf(cnt, 1.0f));
            __threadfence();
            g_done = 0;   // reset for graph replay
        }
    }
}

extern "C" void kernel_launch(void* const* d_in, const int* in_sizes, int n_in,
                              void* d_out, int out_size)
{
    // metadata.txt order: feats (f32), queue (f32), labels (i32).
    // feats and labels have identical element counts — positional ID only.
    const float* feats  = (const float*)d_in[0];
    const float* queue  = (const float*)d_in[1];
    const int*   labels = (const int*)d_in[2];

    cudaFuncSetAttribute(pcl_main_kernel,
                         cudaFuncAttributeMaxDynamicSharedMemorySize, SMEM_BYTES);

    queue_to_bf16_kernel<<<M_CLS * C_DIM / (2 * 256), 256>>>(queue);
    pcl_main_kernel<<<GRID, NTHREADS, SMEM_BYTES>>>(feats, labels, (float*)d_out);
}